// round 12
// baseline (speedup 1.0000x reference)
#include <cuda_runtime.h>
#include <cuda_bf16.h>
#include <math.h>
#include <stdint.h>

#define BATCH 8
#define NPTS  16384
#define M_KV  64
#define TOTM  (BATCH*NPTS)
#define P     16
#define PP    20
typedef unsigned long long ull;

// ======== PTX helpers ========
__device__ __forceinline__ uint32_t smem_u32(const void* p) {
    uint32_t a;
    asm("{ .reg .u64 t; cvta.to.shared.u64 t, %1; cvt.u32.u64 %0, t; }" : "=r"(a) : "l"(p));
    return a;
}
#define CP16(dst, src) asm volatile("cp.async.cg.shared.global [%0], [%1], 16;" :: "r"(dst), "l"(src) : "memory")
#define CP_COMMIT()    asm volatile("cp.async.commit_group;" ::: "memory")
#define CP_WAIT0()     asm volatile("cp.async.wait_group 0;" ::: "memory")
__device__ __forceinline__ void ldsm4(uint32_t* r, uint32_t addr) {
    asm volatile("ldmatrix.sync.aligned.m8n8.x4.shared.b16 {%0,%1,%2,%3}, [%4];"
        : "=r"(r[0]), "=r"(r[1]), "=r"(r[2]), "=r"(r[3]) : "r"(addr));
}
__device__ __forceinline__ void mma16816(float* c, const uint32_t* a, uint32_t b0, uint32_t b1) {
    asm volatile("mma.sync.aligned.m16n8k16.row.col.f32.bf16.bf16.f32 "
        "{%0,%1,%2,%3}, {%4,%5,%6,%7}, {%8,%9}, {%0,%1,%2,%3};"
        : "+f"(c[0]), "+f"(c[1]), "+f"(c[2]), "+f"(c[3])
        : "r"(a[0]), "r"(a[1]), "r"(a[2]), "r"(a[3]), "r"(b0), "r"(b1));
}
#define SW64(o) ((o) ^ (((o) >> 3) & 0x30))
__device__ __forceinline__ void fma2(ull& a, ull x, ull w) {
    asm("fma.rn.f32x2 %0, %1, %2, %0;" : "+l"(a) : "l"(x), "l"(w));
}
__device__ __forceinline__ float fold2(ull v) { float lo,hi; asm("mov.b64 {%0,%1}, %2;" : "=f"(lo),"=f"(hi) : "l"(v)); return lo+hi; }
__device__ __forceinline__ void unpack2(ull v, float& lo, float& hi) { asm("mov.b64 {%0,%1}, %2;" : "=f"(lo),"=f"(hi) : "l"(v)); }
__device__ __forceinline__ ull pack2(float lo, float hi) { ull r; asm("mov.b64 %0, {%1,%2};" : "=l"(r) : "f"(lo),"f"(hi)); return r; }
__device__ __forceinline__ uint32_t packbf(float v0, float v1, float& r0, float& r1) {
    __nv_bfloat16 h0 = __float2bfloat16_rn(v0);
    __nv_bfloat16 h1 = __float2bfloat16_rn(v1);
    r0 = v0 - __bfloat162float(h0);
    r1 = v1 - __bfloat162float(h1);
    unsigned short a = *(unsigned short*)&h0, b = *(unsigned short*)&h1;
    return (uint32_t)a | ((uint32_t)b << 16);
}

// ======== global scratch ========
#define SZ ((size_t)TOTM * 256)
__device__ __nv_bfloat16 g_X0h[SZ], g_X0l[SZ], g_X1h[SZ], g_X1l[SZ], g_Z2h[SZ], g_Z2l[SZ];
__device__ float g_Q[SZ];   // Q for attention; later reused for fp32 MFN output x
__device__ __nv_bfloat16 g_Bh[12*65536], g_Bl[12*65536];
__device__ float g_WkT[65536], g_WvT[65536];
__device__ float g_Kt[BATCH*8*32*M_KV];
__device__ float g_Vt[BATCH*32*256*2];
__device__ __forceinline__ __nv_bfloat16* selH(int s){ return s==0?g_X0h:(s==1?g_X1h:g_Z2h); }
__device__ __forceinline__ __nv_bfloat16* selL(int s){ return s==0?g_X0l:(s==1?g_X1l:g_Z2l); }

// ======== prep kernels ========
__global__ void conv_w(const float* __restrict__ qp_W2, const float* __restrict__ in_W,
                       const float* __restrict__ out_W, const float* __restrict__ net2_W,
                       const float* __restrict__ net1_W) {
    int n = blockIdx.x, mat = blockIdx.y, k = threadIdx.x;
    if (mat >= 12) {
        const float* src = in_W + (size_t)(mat == 12 ? 256 : 512) * 256;
        float* dst = (mat == 12) ? g_WkT : g_WvT;
        dst[k*256 + n] = src[n*256 + k];
        return;
    }
    const float* src;
    switch (mat) {
        case 0: src = qp_W2; break;
        case 1: src = in_W;  break;
        case 2: src = out_W; break;
        default: src = (mat < 8) ? net2_W + (mat-3)*65536 : net1_W + (mat-8)*65536;
    }
    float w = src[n*256 + k];
    __nv_bfloat16 h = __float2bfloat16_rn(w);
    g_Bh[mat*65536 + n*256 + k] = h;
    g_Bl[mat*65536 + n*256 + k] = __float2bfloat16_rn(w - __bfloat162float(h));
}

__global__ void kv_kernel(const float* __restrict__ z_multi,
                          const float* __restrict__ lnkv_g, const float* __restrict__ lnkv_b,
                          const float* __restrict__ in_b) {
    __shared__ float kvn[8][256];
    int t = threadIdx.x, lane = t & 31, w = t >> 5;
    int row0 = blockIdx.x * 8;
    {
        int row = row0 + w;
        float v[8];
        float s = 0.f, ss = 0.f;
        #pragma unroll
        for (int j = 0; j < 8; ++j) {
            v[j] = z_multi[(size_t)row*256 + lane*8 + j];
            s += v[j]; ss += v[j]*v[j];
        }
        #pragma unroll
        for (int o = 16; o; o >>= 1) {
            s  += __shfl_xor_sync(0xffffffffu, s,  o);
            ss += __shfl_xor_sync(0xffffffffu, ss, o);
        }
        float mu = s * (1.f/256.f);
        float rstd = rsqrtf(ss * (1.f/256.f) - mu*mu + 1e-5f);
        #pragma unroll
        for (int j = 0; j < 8; ++j) {
            int d = lane*8 + j;
            kvn[w][d] = (v[j] - mu) * rstd * lnkv_g[d] + lnkv_b[d];
        }
    }
    __syncthreads();
    float aK[8], aV[8];
    float bK = in_b[256+t], bV = in_b[512+t];
    #pragma unroll
    for (int i = 0; i < 8; ++i) { aK[i] = bK; aV[i] = bV; }
    #pragma unroll 4
    for (int d = 0; d < 256; ++d) {
        float wk = g_WkT[d*256 + t];
        float wv = g_WvT[d*256 + t];
        #pragma unroll
        for (int i = 0; i < 8; ++i) {
            float x = kvn[i][d];
            aK[i] += x * wk;
            aV[i] += x * wv;
        }
    }
    #pragma unroll
    for (int i = 0; i < 8; ++i) {
        int row = row0 + i, b = row >> 6, m = row & 63;
        g_Kt[((b*8 + (t>>5))*32 + (t&31))*M_KV + m] = aK[i];
        g_Vt[((b*32 + (m>>1))*256 + t)*2 + (m&1)] = aV[i];
    }
}

// ======== warp-MMA GEMM (templated mode), stage-paired double buffer ========
#define OFF_AL 8192u
#define OFF_BH 16384u
#define OFF_BL 32768u
#define SLAB_BYTES 49152u
#define STAGE_BYTES 98304u
#define GEMM_SMEM (2*98304)
#define MODE_LN 0
#define MODE_Q 1
#define MODE_BIAS 2
#define MODE_BASIS 3
#define MODE_BASISQ 4

template<bool COMPUTE_A>
__device__ __forceinline__ void load_chunk(uint32_t base,
        const __nv_bfloat16* AH, const __nv_bfloat16* AL,
        const __nv_bfloat16* BH, const __nv_bfloat16* BL,
        int m0, int c, int tid,
        float cxp, float cyp,
        const float* __restrict__ qpW1, const float* __restrict__ qpb1) {
    int r = tid >> 2, seg = tid & 3;
    uint32_t sA = base + SW64((uint32_t)(r*64 + seg*16));
    if (COMPUTE_A) {
        int h0 = c*32 + seg*8;
        #pragma unroll
        for (int j2 = 0; j2 < 4; ++j2) {
            int h = h0 + j2*2;
            float4 wv = *(const float4*)(qpW1 + 2*h);
            float2 bv = *(const float2*)(qpb1 + h);
            float u0 = wv.x*cxp + wv.y*cyp + bv.x;
            float u1 = wv.z*cxp + wv.w*cyp + bv.y;
            float v0 = 0.5f*u0*(1.f + erff(u0*0.70710678118654752f));
            float v1 = 0.5f*u1*(1.f + erff(u1*0.70710678118654752f));
            float l0, l1;
            uint32_t hp = packbf(v0, v1, l0, l1);
            __nv_bfloat16 lb0 = __float2bfloat16_rn(l0);
            __nv_bfloat16 lb1 = __float2bfloat16_rn(l1);
            unsigned short a = *(unsigned short*)&lb0, b = *(unsigned short*)&lb1;
            uint32_t lp = (uint32_t)a | ((uint32_t)b << 16);
            asm volatile("st.shared.b32 [%0], %1;" :: "r"(sA + j2*4), "r"(hp) : "memory");
            asm volatile("st.shared.b32 [%0], %1;" :: "r"(sA + OFF_AL + j2*4), "r"(lp) : "memory");
        }
    } else {
        size_t aofs = (size_t)(m0 + r)*256 + c*32 + seg*8;
        CP16(sA, AH + aofs);
        CP16(sA + OFF_AL, AL + aofs);
    }
    #pragma unroll
    for (int it = 0; it < 2; ++it) {
        int row = r + it*128;
        size_t bofs = (size_t)row*256 + c*32 + seg*8;
        uint32_t sB = base + OFF_BH + SW64((uint32_t)(row*64 + seg*16));
        CP16(sB, BH + bofs);
        CP16(sB + 16384u, BL + bofs);
    }
}

template<int MODE>
__global__ void __launch_bounds__(512, 1)
gemm_mma(int L, int nsrc, int srcA1, int srcA2, int matB1, int matB2, int dst,
         const float* __restrict__ bias, float scale,
         const float* __restrict__ lng, const float* __restrict__ lnb,
         const float* __restrict__ gW, const float* __restrict__ gb,
         const float* __restrict__ gmu, const float* __restrict__ gga,
         const float* __restrict__ coords,
         const float* __restrict__ qpW1, const float* __restrict__ qpb1) {
    extern __shared__ char smraw[];
    uint32_t sb = smem_u32(smraw);
    int tid = threadIdx.x, lane = tid & 31, w = tid >> 5;
    int wn = w & 3, wm = w >> 2;
    int m_block = blockIdx.x * 128;

    const __nv_bfloat16* AHs[2] = { selH(srcA1), selH(srcA2) };
    const __nv_bfloat16* ALs[2] = { selL(srcA1), selL(srcA2) };
    const __nv_bfloat16* BHs[2] = { g_Bh + (size_t)matB1*65536, g_Bh + (size_t)matB2*65536 };
    const __nv_bfloat16* BLs[2] = { g_Bl + (size_t)matB1*65536, g_Bl + (size_t)matB2*65536 };

    float cxp = 0.f, cyp = 0.f;
    if (MODE == MODE_LN) {
        float2 xy = *(const float2*)(coords + 2*(m_block + (tid >> 2)));
        cxp = xy.x; cyp = xy.y;
    }
    constexpr bool CA = (MODE == MODE_LN);

    int sub = lane & 7, blk = lane >> 3;
    int rowoff = sub + ((blk & 1) << 3);
    uint32_t koffB = (uint32_t)((blk >> 1) << 4);
    uint32_t aoff[2][2], boff[4][2];
    #pragma unroll
    for (int mt = 0; mt < 2; ++mt)
        #pragma unroll
        for (int kh = 0; kh < 2; ++kh)
            aoff[mt][kh] = SW64((uint32_t)((wm*32 + mt*16 + rowoff)*64 + kh*32) + koffB);
    #pragma unroll
    for (int ng = 0; ng < 4; ++ng)
        #pragma unroll
        for (int kh = 0; kh < 2; ++kh)
            boff[ng][kh] = SW64((uint32_t)((wn*64 + ng*16 + rowoff)*64 + kh*32) + koffB);

    float c[2][8][4];
    #pragma unroll
    for (int mt = 0; mt < 2; ++mt)
        #pragma unroll
        for (int nt = 0; nt < 8; ++nt)
            #pragma unroll
            for (int i = 0; i < 4; ++i) c[mt][nt][i] = 0.f;

    int nst = nsrc * 4;   // stages; each stage = 2 K32 slabs
    load_chunk<CA>(sb, AHs[0], ALs[0], BHs[0], BLs[0], m_block, 0, tid, cxp, cyp, qpW1, qpb1);
    load_chunk<CA>(sb + SLAB_BYTES, AHs[0], ALs[0], BHs[0], BLs[0], m_block, 1, tid, cxp, cyp, qpW1, qpb1);
    CP_COMMIT();

    for (int st = 0; st < nst; ++st) {
        CP_WAIT0();
        __syncthreads();
        if (st + 1 < nst) {
            int g = 2*(st+1), s = g >> 3, cc = g & 7;
            uint32_t nb = sb + ((st+1) & 1)*STAGE_BYTES;
            load_chunk<CA>(nb, AHs[s], ALs[s], BHs[s], BLs[s], m_block, cc, tid, cxp, cyp, qpW1, qpb1);
            load_chunk<CA>(nb + SLAB_BYTES, AHs[s], ALs[s], BHs[s], BLs[s], m_block, cc+1, tid, cxp, cyp, qpW1, qpb1);
            CP_COMMIT();
        }
        uint32_t stbase = sb + (st & 1)*STAGE_BYTES;
        #pragma unroll
        for (int sl = 0; sl < 2; ++sl) {
            uint32_t base = stbase + sl*SLAB_BYTES;
            #pragma unroll
            for (int kh = 0; kh < 2; ++kh) {
                uint32_t ah[2][4], al[2][4];
                ldsm4(ah[0], base + aoff[0][kh]);
                ldsm4(ah[1], base + aoff[1][kh]);
                ldsm4(al[0], base + OFF_AL + aoff[0][kh]);
                ldsm4(al[1], base + OFF_AL + aoff[1][kh]);
                #pragma unroll
                for (int ng = 0; ng < 4; ++ng) {
                    uint32_t bh[4], bl[4];
                    ldsm4(bh, base + OFF_BH + boff[ng][kh]);
                    ldsm4(bl, base + OFF_BL + boff[ng][kh]);
                    #pragma unroll
                    for (int mt = 0; mt < 2; ++mt) {
                        mma16816(c[mt][2*ng],   ah[mt], bh[0], bh[2]);
                        mma16816(c[mt][2*ng+1], ah[mt], bh[1], bh[3]);
                        mma16816(c[mt][2*ng],   al[mt], bh[0], bh[2]);
                        mma16816(c[mt][2*ng+1], al[mt], bh[1], bh[3]);
                        mma16816(c[mt][2*ng],   ah[mt], bl[0], bl[2]);
                        mma16816(c[mt][2*ng+1], ah[mt], bl[1], bl[3]);
                    }
                }
            }
        }
    }
    __syncthreads();

    // ======== fragment-direct epilogue ========
    float* sLN  = (float*)smraw;
    float* sLN2 = sLN + 512;
    int r4 = lane >> 2, kp2 = (lane & 3)*2;

    if (bias) {
        #pragma unroll
        for (int nt = 0; nt < 8; ++nt) {
            float2 bv = *(const float2*)(bias + wn*64 + nt*8 + kp2);
            #pragma unroll
            for (int mt = 0; mt < 2; ++mt) {
                c[mt][nt][0] += bv.x; c[mt][nt][1] += bv.y;
                c[mt][nt][2] += bv.x; c[mt][nt][3] += bv.y;
            }
        }
    }

    float muv[2][2], rsv[2][2];
    if (MODE == MODE_LN) {
        #pragma unroll
        for (int mt = 0; mt < 2; ++mt)
            #pragma unroll
            for (int hf = 0; hf < 2; ++hf) {
                float s = 0.f, ss = 0.f;
                #pragma unroll
                for (int nt = 0; nt < 8; ++nt) {
                    float v0 = c[mt][nt][2*hf], v1 = c[mt][nt][2*hf+1];
                    s += v0 + v1; ss += v0*v0 + v1*v1;
                }
                s  += __shfl_xor_sync(0xffffffffu, s, 1);  s += __shfl_xor_sync(0xffffffffu, s, 2);
                ss += __shfl_xor_sync(0xffffffffu, ss, 1); ss += __shfl_xor_sync(0xffffffffu, ss, 2);
                if ((lane & 3) == 0) {
                    int rl = wm*32 + mt*16 + hf*8 + r4;
                    sLN[rl*4 + wn] = s; sLN2[rl*4 + wn] = ss;
                }
            }
        __syncthreads();
        #pragma unroll
        for (int mt = 0; mt < 2; ++mt)
            #pragma unroll
            for (int hf = 0; hf < 2; ++hf) {
                int rl = wm*32 + mt*16 + hf*8 + r4;
                float S  = sLN[rl*4] + sLN[rl*4+1] + sLN[rl*4+2] + sLN[rl*4+3];
                float SS = sLN2[rl*4] + sLN2[rl*4+1] + sLN2[rl*4+2] + sLN2[rl*4+3];
                float mu = S * (1.f/256.f);
                muv[mt][hf] = mu;
                rsv[mt][hf] = rsqrtf(SS * (1.f/256.f) - mu*mu + 1e-5f);
            }
    }

    float cx[2][2], cy[2][2], rr2[2][2];
    if (MODE == MODE_BASIS || MODE == MODE_BASISQ) {
        #pragma unroll
        for (int mt = 0; mt < 2; ++mt)
            #pragma unroll
            for (int hf = 0; hf < 2; ++hf) {
                int pt = m_block + wm*32 + mt*16 + hf*8 + r4;
                float2 xy = *(const float2*)(coords + 2*pt);
                cx[mt][hf] = xy.x; cy[mt][hf] = xy.y; rr2[mt][hf] = xy.x*xy.x + xy.y*xy.y;
            }
    }

    __nv_bfloat16* oH = selH(dst);
    __nv_bfloat16* oL = selL(dst);
    #pragma unroll
    for (int nt = 0; nt < 8; ++nt) {
        int col = wn*64 + nt*8 + kp2;
        float lg0 = 0.f, lg1 = 0.f, lb0 = 0.f, lb1 = 0.f;
        float wx0=0,wy0=0,wx1=0,wy1=0,b0=0,b1=0,mx0=0,my0=0,mx1=0,my1=0,ga0=0,ga1=0,mu20=0,mu21=0;
        if (MODE == MODE_LN) {
            float2 lg = *(const float2*)(lng + col);
            float2 lb = *(const float2*)(lnb + col);
            lg0 = lg.x; lg1 = lg.y; lb0 = lb.x; lb1 = lb.y;
        } else if (MODE == MODE_BASIS || MODE == MODE_BASISQ) {
            int idx = L*256 + col;
            float4 wv = *(const float4*)(gW + 2*idx);
            float4 mv = *(const float4*)(gmu + 2*idx);
            float2 bv = *(const float2*)(gb + idx);
            float2 gv = *(const float2*)(gga + idx);
            wx0=wv.x; wy0=wv.y; wx1=wv.z; wy1=wv.w;
            mx0=mv.x; my0=mv.y; mx1=mv.z; my1=mv.w;
            b0=bv.x; b1=bv.y; ga0=gv.x; ga1=gv.y;
            mu20 = mx0*mx0 + my0*my0; mu21 = mx1*mx1 + my1*my1;
        }
        #pragma unroll
        for (int mt = 0; mt < 2; ++mt)
            #pragma unroll
            for (int hf = 0; hf < 2; ++hf) {
                int pt = m_block + wm*32 + mt*16 + hf*8 + r4;
                float v0 = c[mt][nt][2*hf], v1 = c[mt][nt][2*hf+1];
                if (MODE == MODE_LN) {
                    v0 = (v0 - muv[mt][hf]) * rsv[mt][hf] * lg0 + lb0;
                    v1 = (v1 - muv[mt][hf]) * rsv[mt][hf] * lg1 + lb1;
                } else if (MODE == MODE_BASIS || MODE == MODE_BASISQ) {
                    float x = cx[mt][hf], y = cy[mt][hf], r2 = rr2[mt][hf];
                    float D0 = r2 + mu20 - 2.f*(x*mx0 + y*my0);
                    float D1 = r2 + mu21 - 2.f*(x*mx1 + y*my1);
                    v0 *= sinf(wx0*x + wy0*y + b0) * __expf(-0.5f*D0*ga0);
                    v1 *= sinf(wx1*x + wy1*y + b1) * __expf(-0.5f*D1*ga1);
                }
                if (MODE == MODE_Q) {
                    *(float2*)(g_Q + (size_t)pt*256 + col) = make_float2(v0*scale, v1*scale);
                } else if (MODE == MODE_BASISQ) {
                    *(float2*)(g_Q + (size_t)pt*256 + col) = make_float2(v0, v1);
                } else {
                    float l0, l1;
                    uint32_t hp = packbf(v0, v1, l0, l1);
                    __nv_bfloat16 lo0 = __float2bfloat16_rn(l0);
                    __nv_bfloat16 lo1 = __float2bfloat16_rn(l1);
                    unsigned short a = *(unsigned short*)&lo0, bsh = *(unsigned short*)&lo1;
                    uint32_t lp = (uint32_t)a | ((uint32_t)bsh << 16);
                    *(uint32_t*)(oH + (size_t)pt*256 + col) = hp;
                    *(uint32_t*)(oL + (size_t)pt*256 + col) = lp;
                }
            }
    }
}

// ======== attention (scalar) ========
#define ATTN_SMF (5120 + P*512)
__global__ void __launch_bounds__(256, 2) attn_kernel() {
    extern __shared__ float smf[];
    float* sA = smf;
    float* sS = sA + 5120;
    int t = threadIdx.x, lane = t & 31, w = t >> 5;
    int bid = blockIdx.x, b = bid >> 10, n0 = (bid & 1023) * P;
    size_t base = (size_t)(b*NPTS + n0) * 256;
    #pragma unroll
    for (int p = 0; p < P; ++p) sA[t*PP + p] = g_Q[base + (size_t)p*256 + t];
    __syncthreads();
    #pragma unroll
    for (int rep = 0; rep < 2; ++rep) {
        int pair = t + rep*256, hh = pair >> 6, m = pair & 63;
        const float* Kp = &g_Kt[((b*8 + hh)*32)*M_KV + m];
        ull a2[8];
        #pragma unroll
        for (int j = 0; j < 8; ++j) a2[j] = 0ull;
        #pragma unroll 4
        for (int k = 0; k < 32; ++k) {
            float kv = Kp[k*M_KV];
            ull kk = pack2(kv, kv);
            const ulonglong2* col = (const ulonglong2*)(sA + (hh*32 + k)*PP);
            #pragma unroll
            for (int q = 0; q < 4; ++q) { ulonglong2 x = col[q]; fma2(a2[2*q], x.x, kk); fma2(a2[2*q+1], x.y, kk); }
        }
        #pragma unroll
        for (int j = 0; j < 8; ++j) {
            float lo, hi; unpack2(a2[j], lo, hi);
            sS[(2*j)*512 + pair] = lo; sS[(2*j+1)*512 + pair] = hi;
        }
    }
    __syncthreads();
    for (int rr = 0; rr < 16; ++rr) {
        int r = w + rr*8, p = r >> 3, hh = r & 7;
        float* bs = &sS[p*512 + hh*64];
        float v0 = bs[lane], v1 = bs[lane+32];
        float mx = fmaxf(v0, v1);
        #pragma unroll
        for (int o = 16; o; o >>= 1) mx = fmaxf(mx, __shfl_xor_sync(0xffffffffu, mx, o));
        float e0 = __expf(v0-mx), e1 = __expf(v1-mx), sum = e0 + e1;
        #pragma unroll
        for (int o = 16; o; o >>= 1) sum += __shfl_xor_sync(0xffffffffu, sum, o);
        float inv = 1.f/sum;
        bs[lane] = e0*inv; bs[lane+32] = e1*inv;
    }
    __syncthreads();
    {
        int hh = t >> 5;
        ull acc[P];
        #pragma unroll
        for (int p = 0; p < P; ++p) acc[p] = 0ull;
        const float* Vb = g_Vt + b*32*512;
        #pragma unroll 2
        for (int m = 0; m < M_KV; m += 2) {
            ull vv = *(const ull*)(Vb + ((m>>1)*256 + t)*2);
            #pragma unroll
            for (int p = 0; p < P; ++p) fma2(acc[p], *(const ull*)(&sS[p*512 + hh*64 + m]), vv);
        }
        #pragma unroll
        for (int p = 0; p < P; ++p) {
            float v = fold2(acc[p]);
            __nv_bfloat16 h = __float2bfloat16_rn(v);
            g_X0h[base + (size_t)p*256 + t] = h;
            g_X0l[base + (size_t)p*256 + t] = __float2bfloat16_rn(v - __bfloat162float(h));
        }
    }
}

// ======== fin + irfft (reads fp32 x from g_Q) ========
__global__ void __launch_bounds__(256, 2)
fin_kernel(const float* __restrict__ fin_W, const float* __restrict__ fin_b,
           float* __restrict__ out) {
    __shared__ float sA[256*PP];
    __shared__ float sF[P*36];
    __shared__ float sTab[32];
    int t = threadIdx.x;
    int bid = blockIdx.x, b = bid >> 10, n0 = (bid & 1023) * P;
    size_t base = (size_t)(b*NPTS + n0) * 256;
    if (t < 16) {
        float sv, cv;
        sincosf(0.39269908169872414f * (float)t, &sv, &cv);
        sTab[2*t] = cv; sTab[2*t+1] = sv;
    }
    #pragma unroll
    for (int p = 0; p < P; ++p)
        sA[t*PP + p] = g_Q[base + (size_t)p*256 + t];
    __syncthreads();
    {
        int g = t >> 2, j = t & 3;
        ull part2[8];
        #pragma unroll
        for (int q = 0; q < 8; ++q) part2[q] = 0ull;
        if (g < 36) {
            const float* Wo = &fin_W[g*256];
            #pragma unroll 4
            for (int k = 0; k < 64; ++k) {
                int h = (k << 2) + j;
                float wv = Wo[h];
                ull ww = pack2(wv, wv);
                const ulonglong2* col = (const ulonglong2*)(sA + h*PP);
                #pragma unroll
                for (int q = 0; q < 4; ++q) { ulonglong2 x = col[q]; fma2(part2[2*q], x.x, ww); fma2(part2[2*q+1], x.y, ww); }
            }
        }
        float part[P];
        #pragma unroll
        for (int q = 0; q < 8; ++q) unpack2(part2[q], part[2*q], part[2*q+1]);
        #pragma unroll
        for (int p = 0; p < P; ++p) {
            part[p] += __shfl_xor_sync(0xffffffffu, part[p], 1);
            part[p] += __shfl_xor_sync(0xffffffffu, part[p], 2);
        }
        if (g < 36 && j == 0) {
            float bb = fin_b[g];
            #pragma unroll
            for (int p = 0; p < P; ++p) sF[p*36 + g] = part[p] + bb;
        }
    }
    __syncthreads();
    {
        int inner = t & 31, p = inner >> 1, c = inner & 1;
        const float* Fp = &sF[p*36];
        #pragma unroll
        for (int it = 0; it < 2; ++it) {
            int tt = (t >> 5) + 8*it;
            float a = Fp[c*2];
            float f8 = Fp[8*4 + c*2];
            a += (tt & 1) ? -f8 : f8;
            #pragma unroll
            for (int fq = 1; fq < 8; ++fq) {
                float re = Fp[fq*4 + c*2], im = Fp[fq*4 + c*2 + 1];
                int k = (fq*tt) & 15;
                a += 2.f * (re*sTab[2*k] - im*sTab[2*k+1]);
            }
            out[(((b*16 + tt)*NPTS) + n0 + p)*2 + c] = 0.25f * a;
        }
    }
}

// ======== launch ========
extern "C" void kernel_launch(void* const* d_in, const int* in_sizes, int n_in,
                              void* d_out, int out_size) {
    const float* z_multi=(const float*)d_in[0];  const float* coords=(const float*)d_in[1];
    const float* gabor_W=(const float*)d_in[2];  const float* gabor_b=(const float*)d_in[3];
    const float* gabor_mu=(const float*)d_in[4]; const float* gabor_ga=(const float*)d_in[5];
    const float* net1_W=(const float*)d_in[6];   const float* net1_b=(const float*)d_in[7];
    const float* net2_W=(const float*)d_in[8];   const float* qp_W1=(const float*)d_in[9];
    const float* qp_b1=(const float*)d_in[10];   const float* qp_W2=(const float*)d_in[11];
    const float* qp_b2=(const float*)d_in[12];   const float* in_W=(const float*)d_in[13];
    const float* in_b=(const float*)d_in[14];    const float* out_W=(const float*)d_in[15];
    const float* out_b=(const float*)d_in[16];   const float* lnq_g=(const float*)d_in[17];
    const float* lnq_b=(const float*)d_in[18];   const float* lnkv_g=(const float*)d_in[19];
    const float* lnkv_b=(const float*)d_in[20];  const float* fin_W=(const float*)d_in[21];
    const float* fin_b=(const float*)d_in[22];
    float* out = (float*)d_out;

    cudaFuncSetAttribute(gemm_mma<MODE_LN>,     cudaFuncAttributeMaxDynamicSharedMemorySize, GEMM_SMEM);
    cudaFuncSetAttribute(gemm_mma<MODE_Q>,      cudaFuncAttributeMaxDynamicSharedMemorySize, GEMM_SMEM);
    cudaFuncSetAttribute(gemm_mma<MODE_BIAS>,   cudaFuncAttributeMaxDynamicSharedMemorySize, GEMM_SMEM);
    cudaFuncSetAttribute(gemm_mma<MODE_BASIS>,  cudaFuncAttributeMaxDynamicSharedMemorySize, GEMM_SMEM);
    cudaFuncSetAttribute(gemm_mma<MODE_BASISQ>, cudaFuncAttributeMaxDynamicSharedMemorySize, GEMM_SMEM);
    cudaFuncSetAttribute(attn_kernel, cudaFuncAttributeMaxDynamicSharedMemorySize, ATTN_SMF*4);

    conv_w<<<dim3(256,14), 256>>>(qp_W2, in_W, out_W, net2_W, net1_W);
    kv_kernel<<<BATCH*M_KV/8, 256>>>(z_multi, lnkv_g, lnkv_b, in_b);

    int G = TOTM/128;
    const float qscale = 0.17677669529663687f;  // 1/sqrt(32)
    gemm_mma<MODE_LN><<<G,512,GEMM_SMEM>>>(0,1, 0,0, 0,0, 1, qp_b2,1.f, lnq_g,lnq_b,
                                           0,0,0,0, coords, qp_W1, qp_b1);
    gemm_mma<MODE_Q><<<G,512,GEMM_SMEM>>>(0,1, 1,0, 1,0, 0, in_b,qscale, 0,0, 0,0,0,0, coords, 0,0);
    attn_kernel<<<BATCH*(NPTS/P), 256, ATTN_SMF*4>>>();
    gemm_mma<MODE_BIAS><<<G,512,GEMM_SMEM>>>(0,1, 0,0, 2,0, 2, out_b,1.f, 0,0, 0,0,0,0, coords, 0,0);
    gemm_mma<MODE_BASIS><<<G,512,GEMM_SMEM>>>(0,1, 2,0, 3,0, 0, (const float*)0,1.f, 0,0,
                                              gabor_W,gabor_b,gabor_mu,gabor_ga, coords, 0,0);
    gemm_mma<MODE_BASIS><<<G,512,GEMM_SMEM>>>(1,2, 0,2, 8,4, 1, net1_b+0,1.f, 0,0,
                                              gabor_W,gabor_b,gabor_mu,gabor_ga, coords, 0,0);
    gemm_mma<MODE_BASIS><<<G,512,GEMM_SMEM>>>(2,2, 1,2, 9,5, 0, net1_b+256,1.f, 0,0,
                                              gabor_W,gabor_b,gabor_mu,gabor_ga, coords, 0,0);
    gemm_mma<MODE_BASIS><<<G,512,GEMM_SMEM>>>(3,2, 0,2, 10,6, 1, net1_b+512,1.f, 0,0,
                                              gabor_W,gabor_b,gabor_mu,gabor_ga, coords, 0,0);
    gemm_mma<MODE_BASISQ><<<G,512,GEMM_SMEM>>>(4,2, 1,2, 11,7, 0, net1_b+768,1.f, 0,0,
                                               gabor_W,gabor_b,gabor_mu,gabor_ga, coords, 0,0);
    fin_kernel<<<BATCH*(NPTS/P), 256>>>(fin_W, fin_b, out);
}

// round 13
// speedup vs baseline: 1.0104x; 1.0104x over previous
#include <cuda_runtime.h>
#include <cuda_bf16.h>
#include <math.h>
#include <stdint.h>

#define BATCH 8
#define NPTS  16384
#define M_KV  64
#define TOTM  (BATCH*NPTS)
#define P     16
#define PP    20
typedef unsigned long long ull;

// ======== PTX helpers ========
__device__ __forceinline__ uint32_t smem_u32(const void* p) {
    uint32_t a;
    asm("{ .reg .u64 t; cvta.to.shared.u64 t, %1; cvt.u32.u64 %0, t; }" : "=r"(a) : "l"(p));
    return a;
}
#define CP16(dst, src) asm volatile("cp.async.cg.shared.global [%0], [%1], 16;" :: "r"(dst), "l"(src) : "memory")
#define CP_COMMIT()    asm volatile("cp.async.commit_group;" ::: "memory")
#define CP_WAIT0()     asm volatile("cp.async.wait_group 0;" ::: "memory")
__device__ __forceinline__ void ldsm4(uint32_t* r, uint32_t addr) {
    asm volatile("ldmatrix.sync.aligned.m8n8.x4.shared.b16 {%0,%1,%2,%3}, [%4];"
        : "=r"(r[0]), "=r"(r[1]), "=r"(r[2]), "=r"(r[3]) : "r"(addr));
}
__device__ __forceinline__ void mma16816(float* c, const uint32_t* a, uint32_t b0, uint32_t b1) {
    asm volatile("mma.sync.aligned.m16n8k16.row.col.f32.bf16.bf16.f32 "
        "{%0,%1,%2,%3}, {%4,%5,%6,%7}, {%8,%9}, {%0,%1,%2,%3};"
        : "+f"(c[0]), "+f"(c[1]), "+f"(c[2]), "+f"(c[3])
        : "r"(a[0]), "r"(a[1]), "r"(a[2]), "r"(a[3]), "r"(b0), "r"(b1));
}
#define SW64(o) ((o) ^ (((o) >> 3) & 0x30))
__device__ __forceinline__ void fma2(ull& a, ull x, ull w) {
    asm("fma.rn.f32x2 %0, %1, %2, %0;" : "+l"(a) : "l"(x), "l"(w));
}
__device__ __forceinline__ float fold2(ull v) { float lo,hi; asm("mov.b64 {%0,%1}, %2;" : "=f"(lo),"=f"(hi) : "l"(v)); return lo+hi; }
__device__ __forceinline__ void unpack2(ull v, float& lo, float& hi) { asm("mov.b64 {%0,%1}, %2;" : "=f"(lo),"=f"(hi) : "l"(v)); }
__device__ __forceinline__ ull pack2(float lo, float hi) { ull r; asm("mov.b64 %0, {%1,%2};" : "=l"(r) : "f"(lo),"f"(hi)); return r; }
__device__ __forceinline__ uint32_t packbf(float v0, float v1, float& r0, float& r1) {
    __nv_bfloat16 h0 = __float2bfloat16_rn(v0);
    __nv_bfloat16 h1 = __float2bfloat16_rn(v1);
    r0 = v0 - __bfloat162float(h0);
    r1 = v1 - __bfloat162float(h1);
    unsigned short a = *(unsigned short*)&h0, b = *(unsigned short*)&h1;
    return (uint32_t)a | ((uint32_t)b << 16);
}
__device__ __forceinline__ uint32_t packlo(float l0, float l1) {
    __nv_bfloat16 a = __float2bfloat16_rn(l0);
    __nv_bfloat16 b = __float2bfloat16_rn(l1);
    unsigned short x = *(unsigned short*)&a, y = *(unsigned short*)&b;
    return (uint32_t)x | ((uint32_t)y << 16);
}

// ======== global scratch ========
#define SZ ((size_t)TOTM * 256)
__device__ __nv_bfloat16 g_X0h[SZ], g_X0l[SZ], g_X1h[SZ], g_X1l[SZ], g_Z2h[SZ], g_Z2l[SZ];
__device__ float g_Q[SZ];   // Q for attention; later reused for fp32 MFN output x
__device__ __nv_bfloat16 g_Bh[12*65536], g_Bl[12*65536];
__device__ float g_WkT[65536], g_WvT[65536];
__device__ float g_Kt[BATCH*8*32*M_KV];
__device__ float g_Vt[BATCH*32*256*2];
__device__ __forceinline__ __nv_bfloat16* selH(int s){ return s==0?g_X0h:(s==1?g_X1h:g_Z2h); }
__device__ __forceinline__ __nv_bfloat16* selL(int s){ return s==0?g_X0l:(s==1?g_X1l:g_Z2l); }

// ======== prep kernels ========
__global__ void conv_w(const float* __restrict__ qp_W2, const float* __restrict__ in_W,
                       const float* __restrict__ out_W, const float* __restrict__ net2_W,
                       const float* __restrict__ net1_W) {
    int n = blockIdx.x, mat = blockIdx.y, k = threadIdx.x;
    if (mat >= 12) {
        const float* src = in_W + (size_t)(mat == 12 ? 256 : 512) * 256;
        float* dst = (mat == 12) ? g_WkT : g_WvT;
        dst[k*256 + n] = src[n*256 + k];
        return;
    }
    const float* src;
    switch (mat) {
        case 0: src = qp_W2; break;
        case 1: src = in_W;  break;
        case 2: src = out_W; break;
        default: src = (mat < 8) ? net2_W + (mat-3)*65536 : net1_W + (mat-8)*65536;
    }
    float w = src[n*256 + k];
    __nv_bfloat16 h = __float2bfloat16_rn(w);
    g_Bh[mat*65536 + n*256 + k] = h;
    g_Bl[mat*65536 + n*256 + k] = __float2bfloat16_rn(w - __bfloat162float(h));
}

__global__ void kv_kernel(const float* __restrict__ z_multi,
                          const float* __restrict__ lnkv_g, const float* __restrict__ lnkv_b,
                          const float* __restrict__ in_b) {
    __shared__ float kvn[8][256];
    int t = threadIdx.x, lane = t & 31, w = t >> 5;
    int row0 = blockIdx.x * 8;
    {
        int row = row0 + w;
        float v[8];
        float s = 0.f, ss = 0.f;
        #pragma unroll
        for (int j = 0; j < 8; ++j) {
            v[j] = z_multi[(size_t)row*256 + lane*8 + j];
            s += v[j]; ss += v[j]*v[j];
        }
        #pragma unroll
        for (int o = 16; o; o >>= 1) {
            s  += __shfl_xor_sync(0xffffffffu, s,  o);
            ss += __shfl_xor_sync(0xffffffffu, ss, o);
        }
        float mu = s * (1.f/256.f);
        float rstd = rsqrtf(ss * (1.f/256.f) - mu*mu + 1e-5f);
        #pragma unroll
        for (int j = 0; j < 8; ++j) {
            int d = lane*8 + j;
            kvn[w][d] = (v[j] - mu) * rstd * lnkv_g[d] + lnkv_b[d];
        }
    }
    __syncthreads();
    float aK[8], aV[8];
    float bK = in_b[256+t], bV = in_b[512+t];
    #pragma unroll
    for (int i = 0; i < 8; ++i) { aK[i] = bK; aV[i] = bV; }
    #pragma unroll 4
    for (int d = 0; d < 256; ++d) {
        float wk = g_WkT[d*256 + t];
        float wv = g_WvT[d*256 + t];
        #pragma unroll
        for (int i = 0; i < 8; ++i) {
            float x = kvn[i][d];
            aK[i] += x * wk;
            aV[i] += x * wv;
        }
    }
    #pragma unroll
    for (int i = 0; i < 8; ++i) {
        int row = row0 + i, b = row >> 6, m = row & 63;
        g_Kt[((b*8 + (t>>5))*32 + (t&31))*M_KV + m] = aK[i];
        g_Vt[((b*32 + (m>>1))*256 + t)*2 + (m&1)] = aV[i];
    }
}

// ======== warp-MMA GEMM (templated mode), stage-paired double buffer ========
#define OFF_AL 8192u
#define OFF_BH 16384u
#define OFF_BL 32768u
#define SLAB_BYTES 49152u
#define STAGE_BYTES 98304u
#define GEMM_SMEM (2*98304)
#define MODE_LN 0
#define MODE_Q 1
#define MODE_BIAS 2

template<bool COMPUTE_A>
__device__ __forceinline__ void load_chunk(uint32_t base,
        const __nv_bfloat16* AH, const __nv_bfloat16* AL,
        const __nv_bfloat16* BH, const __nv_bfloat16* BL,
        int m0, int c, int tid,
        float cxp, float cyp,
        const float* __restrict__ qpW1, const float* __restrict__ qpb1) {
    int r = tid >> 2, seg = tid & 3;
    uint32_t sA = base + SW64((uint32_t)(r*64 + seg*16));
    if (COMPUTE_A) {
        int h0 = c*32 + seg*8;
        #pragma unroll
        for (int j2 = 0; j2 < 4; ++j2) {
            int h = h0 + j2*2;
            float4 wv = *(const float4*)(qpW1 + 2*h);
            float2 bv = *(const float2*)(qpb1 + h);
            float u0 = wv.x*cxp + wv.y*cyp + bv.x;
            float u1 = wv.z*cxp + wv.w*cyp + bv.y;
            float v0 = 0.5f*u0*(1.f + erff(u0*0.70710678118654752f));
            float v1 = 0.5f*u1*(1.f + erff(u1*0.70710678118654752f));
            float l0, l1;
            uint32_t hp = packbf(v0, v1, l0, l1);
            uint32_t lp = packlo(l0, l1);
            asm volatile("st.shared.b32 [%0], %1;" :: "r"(sA + j2*4), "r"(hp) : "memory");
            asm volatile("st.shared.b32 [%0], %1;" :: "r"(sA + OFF_AL + j2*4), "r"(lp) : "memory");
        }
    } else {
        size_t aofs = (size_t)(m0 + r)*256 + c*32 + seg*8;
        CP16(sA, AH + aofs);
        CP16(sA + OFF_AL, AL + aofs);
    }
    #pragma unroll
    for (int it = 0; it < 2; ++it) {
        int row = r + it*128;
        size_t bofs = (size_t)row*256 + c*32 + seg*8;
        uint32_t sB = base + OFF_BH + SW64((uint32_t)(row*64 + seg*16));
        CP16(sB, BH + bofs);
        CP16(sB + 16384u, BL + bofs);
    }
}

template<int MODE>
__global__ void __launch_bounds__(512, 1)
gemm_mma(int nsrc, int srcA1, int matB1, int dst,
         const float* __restrict__ bias, float scale,
         const float* __restrict__ lng, const float* __restrict__ lnb,
         const float* __restrict__ coords,
         const float* __restrict__ qpW1, const float* __restrict__ qpb1) {
    extern __shared__ char smraw[];
    uint32_t sb = smem_u32(smraw);
    int tid = threadIdx.x, lane = tid & 31, w = tid >> 5;
    int wn = w & 3, wm = w >> 2;
    int m_block = blockIdx.x * 128;

    const __nv_bfloat16* AH = selH(srcA1);
    const __nv_bfloat16* AL = selL(srcA1);
    const __nv_bfloat16* BH = g_Bh + (size_t)matB1*65536;
    const __nv_bfloat16* BL = g_Bl + (size_t)matB1*65536;

    float cxp = 0.f, cyp = 0.f;
    if (MODE == MODE_LN) {
        float2 xy = *(const float2*)(coords + 2*(m_block + (tid >> 2)));
        cxp = xy.x; cyp = xy.y;
    }
    constexpr bool CA = (MODE == MODE_LN);

    int sub = lane & 7, blk = lane >> 3;
    int rowoff = sub + ((blk & 1) << 3);
    uint32_t koffB = (uint32_t)((blk >> 1) << 4);
    uint32_t aoff[2][2], boff[4][2];
    #pragma unroll
    for (int mt = 0; mt < 2; ++mt)
        #pragma unroll
        for (int kh = 0; kh < 2; ++kh)
            aoff[mt][kh] = SW64((uint32_t)((wm*32 + mt*16 + rowoff)*64 + kh*32) + koffB);
    #pragma unroll
    for (int ng = 0; ng < 4; ++ng)
        #pragma unroll
        for (int kh = 0; kh < 2; ++kh)
            boff[ng][kh] = SW64((uint32_t)((wn*64 + ng*16 + rowoff)*64 + kh*32) + koffB);

    float c[2][8][4];
    #pragma unroll
    for (int mt = 0; mt < 2; ++mt)
        #pragma unroll
        for (int nt = 0; nt < 8; ++nt)
            #pragma unroll
            for (int i = 0; i < 4; ++i) c[mt][nt][i] = 0.f;

    int nst = nsrc * 4;
    load_chunk<CA>(sb, AH, AL, BH, BL, m_block, 0, tid, cxp, cyp, qpW1, qpb1);
    load_chunk<CA>(sb + SLAB_BYTES, AH, AL, BH, BL, m_block, 1, tid, cxp, cyp, qpW1, qpb1);
    CP_COMMIT();

    for (int st = 0; st < nst; ++st) {
        CP_WAIT0();
        __syncthreads();
        if (st + 1 < nst) {
            int g = 2*(st+1), cc = g & 7;
            uint32_t nb = sb + ((st+1) & 1)*STAGE_BYTES;
            load_chunk<CA>(nb, AH, AL, BH, BL, m_block, cc, tid, cxp, cyp, qpW1, qpb1);
            load_chunk<CA>(nb + SLAB_BYTES, AH, AL, BH, BL, m_block, cc+1, tid, cxp, cyp, qpW1, qpb1);
            CP_COMMIT();
        }
        uint32_t stbase = sb + (st & 1)*STAGE_BYTES;
        #pragma unroll
        for (int sl = 0; sl < 2; ++sl) {
            uint32_t base = stbase + sl*SLAB_BYTES;
            #pragma unroll
            for (int kh = 0; kh < 2; ++kh) {
                uint32_t ah[2][4], al[2][4];
                ldsm4(ah[0], base + aoff[0][kh]);
                ldsm4(ah[1], base + aoff[1][kh]);
                ldsm4(al[0], base + OFF_AL + aoff[0][kh]);
                ldsm4(al[1], base + OFF_AL + aoff[1][kh]);
                #pragma unroll
                for (int ng = 0; ng < 4; ++ng) {
                    uint32_t bh[4], bl[4];
                    ldsm4(bh, base + OFF_BH + boff[ng][kh]);
                    ldsm4(bl, base + OFF_BL + boff[ng][kh]);
                    #pragma unroll
                    for (int mt = 0; mt < 2; ++mt) {
                        mma16816(c[mt][2*ng],   ah[mt], bh[0], bh[2]);
                        mma16816(c[mt][2*ng+1], ah[mt], bh[1], bh[3]);
                        mma16816(c[mt][2*ng],   al[mt], bh[0], bh[2]);
                        mma16816(c[mt][2*ng+1], al[mt], bh[1], bh[3]);
                        mma16816(c[mt][2*ng],   ah[mt], bl[0], bl[2]);
                        mma16816(c[mt][2*ng+1], ah[mt], bl[1], bl[3]);
                    }
                }
            }
        }
    }
    __syncthreads();

    // ======== fragment-direct epilogue ========
    float* sLN  = (float*)smraw;
    float* sLN2 = sLN + 512;
    int r4 = lane >> 2, kp2 = (lane & 3)*2;

    if (bias) {
        #pragma unroll
        for (int nt = 0; nt < 8; ++nt) {
            float2 bv = *(const float2*)(bias + wn*64 + nt*8 + kp2);
            #pragma unroll
            for (int mt = 0; mt < 2; ++mt) {
                c[mt][nt][0] += bv.x; c[mt][nt][1] += bv.y;
                c[mt][nt][2] += bv.x; c[mt][nt][3] += bv.y;
            }
        }
    }

    float muv[2][2], rsv[2][2];
    if (MODE == MODE_LN) {
        #pragma unroll
        for (int mt = 0; mt < 2; ++mt)
            #pragma unroll
            for (int hf = 0; hf < 2; ++hf) {
                float s = 0.f, ss = 0.f;
                #pragma unroll
                for (int nt = 0; nt < 8; ++nt) {
                    float v0 = c[mt][nt][2*hf], v1 = c[mt][nt][2*hf+1];
                    s += v0 + v1; ss += v0*v0 + v1*v1;
                }
                s  += __shfl_xor_sync(0xffffffffu, s, 1);  s += __shfl_xor_sync(0xffffffffu, s, 2);
                ss += __shfl_xor_sync(0xffffffffu, ss, 1); ss += __shfl_xor_sync(0xffffffffu, ss, 2);
                if ((lane & 3) == 0) {
                    int rl = wm*32 + mt*16 + hf*8 + r4;
                    sLN[rl*4 + wn] = s; sLN2[rl*4 + wn] = ss;
                }
            }
        __syncthreads();
        #pragma unroll
        for (int mt = 0; mt < 2; ++mt)
            #pragma unroll
            for (int hf = 0; hf < 2; ++hf) {
                int rl = wm*32 + mt*16 + hf*8 + r4;
                float S  = sLN[rl*4] + sLN[rl*4+1] + sLN[rl*4+2] + sLN[rl*4+3];
                float SS = sLN2[rl*4] + sLN2[rl*4+1] + sLN2[rl*4+2] + sLN2[rl*4+3];
                float mu = S * (1.f/256.f);
                muv[mt][hf] = mu;
                rsv[mt][hf] = rsqrtf(SS * (1.f/256.f) - mu*mu + 1e-5f);
            }
    }

    __nv_bfloat16* oH = selH(dst);
    __nv_bfloat16* oL = selL(dst);
    #pragma unroll
    for (int nt = 0; nt < 8; ++nt) {
        int col = wn*64 + nt*8 + kp2;
        float lg0 = 0.f, lg1 = 0.f, lb0 = 0.f, lb1 = 0.f;
        if (MODE == MODE_LN) {
            float2 lg = *(const float2*)(lng + col);
            float2 lb = *(const float2*)(lnb + col);
            lg0 = lg.x; lg1 = lg.y; lb0 = lb.x; lb1 = lb.y;
        }
        #pragma unroll
        for (int mt = 0; mt < 2; ++mt)
            #pragma unroll
            for (int hf = 0; hf < 2; ++hf) {
                int pt = m_block + wm*32 + mt*16 + hf*8 + r4;
                float v0 = c[mt][nt][2*hf], v1 = c[mt][nt][2*hf+1];
                if (MODE == MODE_LN) {
                    v0 = (v0 - muv[mt][hf]) * rsv[mt][hf] * lg0 + lb0;
                    v1 = (v1 - muv[mt][hf]) * rsv[mt][hf] * lg1 + lb1;
                }
                if (MODE == MODE_Q) {
                    *(float2*)(g_Q + (size_t)pt*256 + col) = make_float2(v0*scale, v1*scale);
                } else {
                    float l0, l1;
                    uint32_t hp = packbf(v0, v1, l0, l1);
                    uint32_t lp = packlo(l0, l1);
                    *(uint32_t*)(oH + (size_t)pt*256 + col) = hp;
                    *(uint32_t*)(oL + (size_t)pt*256 + col) = lp;
                }
            }
    }
}

// ======== fused MFN kernel: L0..L4 with persistent x in smem ========
// smem: x buffer 8 chunks x (h 8KB @ +0, l 8KB @ +8192) = 131072
//       stages: 2 x 48KB slab (A h@0, A l@8192, Bh@16384, Bl@32768)
#define FX_BYTES 131072u
#define FSLAB 49152u
#define FUSED_SMEM (131072 + 2*49152)

__global__ void __launch_bounds__(512, 1)
mfn_fused(const float* __restrict__ net1_b,
          const float* __restrict__ gW, const float* __restrict__ gb,
          const float* __restrict__ gmu, const float* __restrict__ gga,
          const float* __restrict__ coords) {
    extern __shared__ char smraw[];
    uint32_t sb = smem_u32(smraw);
    uint32_t stoff = sb + FX_BYTES;
    int tid = threadIdx.x, lane = tid & 31, w = tid >> 5;
    int wn = w & 3, wm = w >> 2;
    int m_block = blockIdx.x * 128;

    int sub = lane & 7, blk = lane >> 3;
    int rowoff = sub + ((blk & 1) << 3);
    uint32_t koffB = (uint32_t)((blk >> 1) << 4);
    uint32_t aoff[2][2], boff[4][2];
    #pragma unroll
    for (int mt = 0; mt < 2; ++mt)
        #pragma unroll
        for (int kh = 0; kh < 2; ++kh)
            aoff[mt][kh] = SW64((uint32_t)((wm*32 + mt*16 + rowoff)*64 + kh*32) + koffB);
    #pragma unroll
    for (int ng = 0; ng < 4; ++ng)
        #pragma unroll
        for (int kh = 0; kh < 2; ++kh)
            boff[ng][kh] = SW64((uint32_t)((wn*64 + ng*16 + rowoff)*64 + kh*32) + koffB);

    int r4 = lane >> 2, kp2 = (lane & 3)*2;
    // per-row coords
    float cx[2][2], cy[2][2], rr2[2][2];
    #pragma unroll
    for (int mt = 0; mt < 2; ++mt)
        #pragma unroll
        for (int hf = 0; hf < 2; ++hf) {
            int pt = m_block + wm*32 + mt*16 + hf*8 + r4;
            float2 xy = *(const float2*)(coords + 2*pt);
            cx[mt][hf] = xy.x; cy[mt][hf] = xy.y; rr2[mt][hf] = xy.x*xy.x + xy.y*xy.y;
        }

    // prefetch helper: load chunk for (L, i) into stage buffer stb
    auto prefetch = [&](int L, int i, uint32_t stb) {
        bool loadA; int ch, matB;
        if (L == 0)      { loadA = true;  ch = i;     matB = 3; }
        else if (i < 8)  { loadA = false; ch = i;     matB = 8 + (L-1); }
        else             { loadA = true;  ch = i - 8; matB = 3 + L; }
        const __nv_bfloat16* BHp = g_Bh + (size_t)matB*65536;
        const __nv_bfloat16* BLp = g_Bl + (size_t)matB*65536;
        int r = tid >> 2, seg = tid & 3;
        size_t go = (size_t)ch*32 + seg*8;
        if (loadA) {
            size_t aofs = (size_t)(m_block + r)*256 + go;
            uint32_t sA = stb + SW64((uint32_t)(r*64 + seg*16));
            CP16(sA, g_Z2h + aofs);
            CP16(sA + OFF_AL, g_Z2l + aofs);
        }
        #pragma unroll
        for (int it = 0; it < 2; ++it) {
            int row = r + it*128;
            uint32_t sB = stb + OFF_BH + SW64((uint32_t)(row*64 + seg*16));
            CP16(sB, BHp + (size_t)row*256 + go);
            CP16(sB + 16384u, BLp + (size_t)row*256 + go);
        }
    };

    float c[2][8][4];
    int s = 0;
    prefetch(0, 0, stoff);
    CP_COMMIT();

    for (int L = 0; L <= 4; ++L) {
        int np = (L == 0) ? 8 : 16;
        #pragma unroll
        for (int mt = 0; mt < 2; ++mt)
            #pragma unroll
            for (int nt = 0; nt < 8; ++nt)
                #pragma unroll
                for (int i = 0; i < 4; ++i) c[mt][nt][i] = 0.f;

        for (int i = 0; i < np; ++i) {
            CP_WAIT0();
            __syncthreads();
            {   // prefetch next step
                int nL = L, ni = i + 1;
                if (ni == np) { nL = L + 1; ni = 0; }
                if (nL <= 4) {
                    prefetch(nL, ni, stoff + (uint32_t)((s+1) & 1)*FSLAB);
                    CP_COMMIT();
                }
            }
            bool isx = (L > 0 && i < 8);
            uint32_t stb = stoff + (uint32_t)(s & 1)*FSLAB;
            uint32_t Abase = isx ? (sb + (uint32_t)i*16384u) : stb;
            uint32_t Bbase = stb;
            #pragma unroll
            for (int kh = 0; kh < 2; ++kh) {
                uint32_t ah[2][4], al[2][4];
                ldsm4(ah[0], Abase + aoff[0][kh]);
                ldsm4(ah[1], Abase + aoff[1][kh]);
                ldsm4(al[0], Abase + OFF_AL + aoff[0][kh]);
                ldsm4(al[1], Abase + OFF_AL + aoff[1][kh]);
                #pragma unroll
                for (int ng = 0; ng < 4; ++ng) {
                    uint32_t bh[4], bl[4];
                    ldsm4(bh, Bbase + OFF_BH + boff[ng][kh]);
                    ldsm4(bl, Bbase + OFF_BL + boff[ng][kh]);
                    #pragma unroll
                    for (int mt = 0; mt < 2; ++mt) {
                        mma16816(c[mt][2*ng],   ah[mt], bh[0], bh[2]);
                        mma16816(c[mt][2*ng+1], ah[mt], bh[1], bh[3]);
                        mma16816(c[mt][2*ng],   al[mt], bh[0], bh[2]);
                        mma16816(c[mt][2*ng+1], al[mt], bh[1], bh[3]);
                        mma16816(c[mt][2*ng],   ah[mt], bl[0], bl[2]);
                        mma16816(c[mt][2*ng+1], ah[mt], bl[1], bl[3]);
                    }
                }
            }
            ++s;
        }
        __syncthreads();   // all reads of x done before overwrite

        // ---- epilogue layer L: basis multiply, write back ----
        #pragma unroll
        for (int nt = 0; nt < 8; ++nt) {
            int col = wn*64 + nt*8 + kp2;
            if (L > 0) {
                float2 bv = *(const float2*)(net1_b + (L-1)*256 + col);
                #pragma unroll
                for (int mt = 0; mt < 2; ++mt) {
                    c[mt][nt][0] += bv.x; c[mt][nt][1] += bv.y;
                    c[mt][nt][2] += bv.x; c[mt][nt][3] += bv.y;
                }
            }
            int idx = L*256 + col;
            float4 wv = *(const float4*)(gW + 2*idx);
            float4 mv = *(const float4*)(gmu + 2*idx);
            float2 bb = *(const float2*)(gb + idx);
            float2 gv = *(const float2*)(gga + idx);
            float mu20 = mv.x*mv.x + mv.y*mv.y;
            float mu21 = mv.z*mv.z + mv.w*mv.w;
            #pragma unroll
            for (int mt = 0; mt < 2; ++mt)
                #pragma unroll
                for (int hf = 0; hf < 2; ++hf) {
                    float x = cx[mt][hf], y = cy[mt][hf], r2 = rr2[mt][hf];
                    float D0 = r2 + mu20 - 2.f*(x*mv.x + y*mv.y);
                    float D1 = r2 + mu21 - 2.f*(x*mv.z + y*mv.w);
                    float v0 = c[mt][nt][2*hf] * (sinf(wv.x*x + wv.y*y + bb.x) * __expf(-0.5f*D0*gv.x));
                    float v1 = c[mt][nt][2*hf+1] * (sinf(wv.z*x + wv.w*y + bb.y) * __expf(-0.5f*D1*gv.y));
                    if (L < 4) {
                        float l0, l1;
                        uint32_t hp = packbf(v0, v1, l0, l1);
                        uint32_t lp = packlo(l0, l1);
                        int rl = wm*32 + mt*16 + hf*8 + r4;
                        uint32_t xo = sb + (uint32_t)(col >> 5)*16384u
                                    + SW64((uint32_t)(rl*64 + (col & 31)*2));
                        asm volatile("st.shared.b32 [%0], %1;" :: "r"(xo), "r"(hp) : "memory");
                        asm volatile("st.shared.b32 [%0], %1;" :: "r"(xo + OFF_AL), "r"(lp) : "memory");
                    } else {
                        int pt = m_block + wm*32 + mt*16 + hf*8 + r4;
                        *(float2*)(g_Q + (size_t)pt*256 + col) = make_float2(v0, v1);
                    }
                }
        }
        // next layer's first step does CP_WAIT0+__syncthreads, ordering these writes
    }
}

// ======== attention (scalar) ========
#define ATTN_SMF (5120 + P*512)
__global__ void __launch_bounds__(256, 2) attn_kernel() {
    extern __shared__ float smf[];
    float* sA = smf;
    float* sS = sA + 5120;
    int t = threadIdx.x, lane = t & 31, w = t >> 5;
    int bid = blockIdx.x, b = bid >> 10, n0 = (bid & 1023) * P;
    size_t base = (size_t)(b*NPTS + n0) * 256;
    #pragma unroll
    for (int p = 0; p < P; ++p) sA[t*PP + p] = g_Q[base + (size_t)p*256 + t];
    __syncthreads();
    #pragma unroll
    for (int rep = 0; rep < 2; ++rep) {
        int pair = t + rep*256, hh = pair >> 6, m = pair & 63;
        const float* Kp = &g_Kt[((b*8 + hh)*32)*M_KV + m];
        ull a2[8];
        #pragma unroll
        for (int j = 0; j < 8; ++j) a2[j] = 0ull;
        #pragma unroll 4
        for (int k = 0; k < 32; ++k) {
            float kv = Kp[k*M_KV];
            ull kk = pack2(kv, kv);
            const ulonglong2* col = (const ulonglong2*)(sA + (hh*32 + k)*PP);
            #pragma unroll
            for (int q = 0; q < 4; ++q) { ulonglong2 x = col[q]; fma2(a2[2*q], x.x, kk); fma2(a2[2*q+1], x.y, kk); }
        }
        #pragma unroll
        for (int j = 0; j < 8; ++j) {
            float lo, hi; unpack2(a2[j], lo, hi);
            sS[(2*j)*512 + pair] = lo; sS[(2*j+1)*512 + pair] = hi;
        }
    }
    __syncthreads();
    for (int rr = 0; rr < 16; ++rr) {
        int r = w + rr*8, p = r >> 3, hh = r & 7;
        float* bs = &sS[p*512 + hh*64];
        float v0 = bs[lane], v1 = bs[lane+32];
        float mx = fmaxf(v0, v1);
        #pragma unroll
        for (int o = 16; o; o >>= 1) mx = fmaxf(mx, __shfl_xor_sync(0xffffffffu, mx, o));
        float e0 = __expf(v0-mx), e1 = __expf(v1-mx), sum = e0 + e1;
        #pragma unroll
        for (int o = 16; o; o >>= 1) sum += __shfl_xor_sync(0xffffffffu, sum, o);
        float inv = 1.f/sum;
        bs[lane] = e0*inv; bs[lane+32] = e1*inv;
    }
    __syncthreads();
    {
        int hh = t >> 5;
        ull acc[P];
        #pragma unroll
        for (int p = 0; p < P; ++p) acc[p] = 0ull;
        const float* Vb = g_Vt + b*32*512;
        #pragma unroll 2
        for (int m = 0; m < M_KV; m += 2) {
            ull vv = *(const ull*)(Vb + ((m>>1)*256 + t)*2);
            #pragma unroll
            for (int p = 0; p < P; ++p) fma2(acc[p], *(const ull*)(&sS[p*512 + hh*64 + m]), vv);
        }
        #pragma unroll
        for (int p = 0; p < P; ++p) {
            float v = fold2(acc[p]);
            __nv_bfloat16 h = __float2bfloat16_rn(v);
            g_X0h[base + (size_t)p*256 + t] = h;
            g_X0l[base + (size_t)p*256 + t] = __float2bfloat16_rn(v - __bfloat162float(h));
        }
    }
}

// ======== fin + irfft (reads fp32 x from g_Q) ========
__global__ void __launch_bounds__(256, 2)
fin_kernel(const float* __restrict__ fin_W, const float* __restrict__ fin_b,
           float* __restrict__ out) {
    __shared__ float sA[256*PP];
    __shared__ float sF[P*36];
    __shared__ float sTab[32];
    int t = threadIdx.x;
    int bid = blockIdx.x, b = bid >> 10, n0 = (bid & 1023) * P;
    size_t base = (size_t)(b*NPTS + n0) * 256;
    if (t < 16) {
        float sv, cv;
        sincosf(0.39269908169872414f * (float)t, &sv, &cv);
        sTab[2*t] = cv; sTab[2*t+1] = sv;
    }
    #pragma unroll
    for (int p = 0; p < P; ++p)
        sA[t*PP + p] = g_Q[base + (size_t)p*256 + t];
    __syncthreads();
    {
        int g = t >> 2, j = t & 3;
        ull part2[8];
        #pragma unroll
        for (int q = 0; q < 8; ++q) part2[q] = 0ull;
        if (g < 36) {
            const float* Wo = &fin_W[g*256];
            #pragma unroll 4
            for (int k = 0; k < 64; ++k) {
                int h = (k << 2) + j;
                float wv = Wo[h];
                ull ww = pack2(wv, wv);
                const ulonglong2* col = (const ulonglong2*)(sA + h*PP);
                #pragma unroll
                for (int q = 0; q < 4; ++q) { ulonglong2 x = col[q]; fma2(part2[2*q], x.x, ww); fma2(part2[2*q+1], x.y, ww); }
            }
        }
        float part[P];
        #pragma unroll
        for (int q = 0; q < 8; ++q) unpack2(part2[q], part[2*q], part[2*q+1]);
        #pragma unroll
        for (int p = 0; p < P; ++p) {
            part[p] += __shfl_xor_sync(0xffffffffu, part[p], 1);
            part[p] += __shfl_xor_sync(0xffffffffu, part[p], 2);
        }
        if (g < 36 && j == 0) {
            float bb = fin_b[g];
            #pragma unroll
            for (int p = 0; p < P; ++p) sF[p*36 + g] = part[p] + bb;
        }
    }
    __syncthreads();
    {
        int inner = t & 31, p = inner >> 1, c = inner & 1;
        const float* Fp = &sF[p*36];
        #pragma unroll
        for (int it = 0; it < 2; ++it) {
            int tt = (t >> 5) + 8*it;
            float a = Fp[c*2];
            float f8 = Fp[8*4 + c*2];
            a += (tt & 1) ? -f8 : f8;
            #pragma unroll
            for (int fq = 1; fq < 8; ++fq) {
                float re = Fp[fq*4 + c*2], im = Fp[fq*4 + c*2 + 1];
                int k = (fq*tt) & 15;
                a += 2.f * (re*sTab[2*k] - im*sTab[2*k+1]);
            }
            out[(((b*16 + tt)*NPTS) + n0 + p)*2 + c] = 0.25f * a;
        }
    }
}

// ======== launch ========
extern "C" void kernel_launch(void* const* d_in, const int* in_sizes, int n_in,
                              void* d_out, int out_size) {
    const float* z_multi=(const float*)d_in[0];  const float* coords=(const float*)d_in[1];
    const float* gabor_W=(const float*)d_in[2];  const float* gabor_b=(const float*)d_in[3];
    const float* gabor_mu=(const float*)d_in[4]; const float* gabor_ga=(const float*)d_in[5];
    const float* net1_W=(const float*)d_in[6];   const float* net1_b=(const float*)d_in[7];
    const float* net2_W=(const float*)d_in[8];   const float* qp_W1=(const float*)d_in[9];
    const float* qp_b1=(const float*)d_in[10];   const float* qp_W2=(const float*)d_in[11];
    const float* qp_b2=(const float*)d_in[12];   const float* in_W=(const float*)d_in[13];
    const float* in_b=(const float*)d_in[14];    const float* out_W=(const float*)d_in[15];
    const float* out_b=(const float*)d_in[16];   const float* lnq_g=(const float*)d_in[17];
    const float* lnq_b=(const float*)d_in[18];   const float* lnkv_g=(const float*)d_in[19];
    const float* lnkv_b=(const float*)d_in[20];  const float* fin_W=(const float*)d_in[21];
    const float* fin_b=(const float*)d_in[22];
    float* out = (float*)d_out;

    cudaFuncSetAttribute(gemm_mma<MODE_LN>,   cudaFuncAttributeMaxDynamicSharedMemorySize, GEMM_SMEM);
    cudaFuncSetAttribute(gemm_mma<MODE_Q>,    cudaFuncAttributeMaxDynamicSharedMemorySize, GEMM_SMEM);
    cudaFuncSetAttribute(gemm_mma<MODE_BIAS>, cudaFuncAttributeMaxDynamicSharedMemorySize, GEMM_SMEM);
    cudaFuncSetAttribute(mfn_fused,           cudaFuncAttributeMaxDynamicSharedMemorySize, FUSED_SMEM);
    cudaFuncSetAttribute(attn_kernel, cudaFuncAttributeMaxDynamicSharedMemorySize, ATTN_SMF*4);

    conv_w<<<dim3(256,14), 256>>>(qp_W2, in_W, out_W, net2_W, net1_W);
    kv_kernel<<<BATCH*M_KV/8, 256>>>(z_multi, lnkv_g, lnkv_b, in_b);

    int G = TOTM/128;
    const float qscale = 0.17677669529663687f;  // 1/sqrt(32)
    // q = LN(gelu(x0@qpW1+b1) @ qpW2^T + b2) -> X1
    gemm_mma<MODE_LN><<<G,512,GEMM_SMEM>>>(1, 0, 0, 1, qp_b2, 1.f, lnq_g, lnq_b, coords, qp_W1, qp_b1);
    // Q = (X1 @ Wq^T + bq)*scale -> g_Q
    gemm_mma<MODE_Q><<<G,512,GEMM_SMEM>>>(1, 1, 1, 0, in_b, qscale, 0, 0, coords, 0, 0);
    attn_kernel<<<BATCH*(NPTS/P), 256, ATTN_SMF*4>>>();
    // z = ctx @ outW^T + out_b -> Z2
    gemm_mma<MODE_BIAS><<<G,512,GEMM_SMEM>>>(1, 0, 2, 2, out_b, 1.f, 0, 0, coords, 0, 0);
    // fused MFN L0..L4 -> fp32 x in g_Q
    mfn_fused<<<G,512,FUSED_SMEM>>>(net1_b, gabor_W, gabor_b, gabor_mu, gabor_ga, coords);
    fin_kernel<<<BATCH*(NPTS/P), 256>>>(fin_W, fin_b, out);
}